// round 1
// baseline (speedup 1.0000x reference)
#include <cuda_runtime.h>
#include <cstdint>

#define REG_COEF 0.001f

// Problem dims (fixed by the dataset)
#define BDIM 8192
#define KDIM 1024
#define DDIM 64
#define NDIM (DDIM*DDIM)   // 4096

// Scratch: weights W[B,K] (tf32-rounded fp32) and tf32-rounded copy of G
__device__ float g_W[(size_t)BDIM * KDIM];
__device__ float g_G[(size_t)KDIM * NDIM];

__device__ __forceinline__ uint32_t f2tf32(float x) {
    uint32_t r;
    asm("cvt.rna.tf32.f32 %0, %1;" : "=r"(r) : "f"(x));
    return r;
}

// ---------------------------------------------------------------------------
// Phase 0: RN-convert g_inv_c (fp32) -> tf32-valued fp32 scratch
// ---------------------------------------------------------------------------
__global__ void convert_g_kernel(const float* __restrict__ g) {
    size_t i = ((size_t)blockIdx.x * 256 + threadIdx.x) * 4;
    float4 v = *(const float4*)(g + i);
    uint4 o;
    o.x = f2tf32(v.x); o.y = f2tf32(v.y); o.z = f2tf32(v.z); o.w = f2tf32(v.w);
    *(uint4*)(g_G + i) = o;
}

// ---------------------------------------------------------------------------
// Phase 1: W[b,k] = exp(-bw_k * max(||q_b||^2 + ||c_k||^2 - 2 q_b.c_k, 0))
// 64x64 tile per block, 256 threads, 4x4 micro-tile per thread.
// Tiles stored TRANSPOSED in smem ([dim][row]) for vectorized LDS.128 in the
// FMA loop (q reads broadcast, c reads conflict-light).
// ---------------------------------------------------------------------------
__global__ __launch_bounds__(256) void weights_kernel(
    const float* __restrict__ q, const float* __restrict__ c,
    const float* __restrict__ bw)
{
    __shared__ float qs[64][68];   // [kdim][row]
    __shared__ float cs[64][68];   // [kdim][row]
    __shared__ float sqq[64], sqc[64], bws[64];

    int t  = threadIdx.x;
    int bx = blockIdx.x;   // K tile (16)
    int by = blockIdx.y;   // B tile (128)

    // Load both 64x64 tiles, transposing into smem
#pragma unroll
    for (int i = 0; i < 4; i++) {
        int ch  = t + i * 256;          // 0..1023
        int row = ch >> 4;              // 64 rows, 16 float4-chunks per row
        int cc  = ch & 15;
        float4 v = *(const float4*)(q + ((size_t)(by * 64 + row)) * DDIM + cc * 4);
        qs[cc*4+0][row] = v.x; qs[cc*4+1][row] = v.y;
        qs[cc*4+2][row] = v.z; qs[cc*4+3][row] = v.w;
        float4 w = *(const float4*)(c + ((size_t)(bx * 64 + row)) * DDIM + cc * 4);
        cs[cc*4+0][row] = w.x; cs[cc*4+1][row] = w.y;
        cs[cc*4+2][row] = w.z; cs[cc*4+3][row] = w.w;
    }
    if (t < 64) bws[t] = bw[bx * 64 + t];
    __syncthreads();

    // Row norms (threads 0..63 -> q rows, 64..127 -> c rows)
    if (t < 64) {
        float s = 0.f;
#pragma unroll 8
        for (int kk = 0; kk < 64; kk++) { float v = qs[kk][t]; s = fmaf(v, v, s); }
        sqq[t] = s;
    } else if (t < 128) {
        int r = t - 64;
        float s = 0.f;
#pragma unroll 8
        for (int kk = 0; kk < 64; kk++) { float v = cs[kk][r]; s = fmaf(v, v, s); }
        sqc[r] = s;
    }
    __syncthreads();

    int tr = t >> 4;   // 0..15 -> q micro rows
    int tc = t & 15;   // 0..15 -> c micro rows

    float acc[4][4];
#pragma unroll
    for (int i = 0; i < 4; i++)
#pragma unroll
        for (int j = 0; j < 4; j++) acc[i][j] = 0.f;

#pragma unroll 4
    for (int kk = 0; kk < 64; kk++) {
        float4 a = *(const float4*)&qs[kk][tr * 4];
        float4 b = *(const float4*)&cs[kk][tc * 4];
        float av[4] = {a.x, a.y, a.z, a.w};
        float bv[4] = {b.x, b.y, b.z, b.w};
#pragma unroll
        for (int i = 0; i < 4; i++)
#pragma unroll
            for (int j = 0; j < 4; j++)
                acc[i][j] = fmaf(av[i], bv[j], acc[i][j]);
    }

    int gb = by * 64 + tr * 4;
    int gk = bx * 64 + tc * 4;
#pragma unroll
    for (int i = 0; i < 4; i++) {
        float aq = sqq[tr * 4 + i];
        uint4 o;
        float d2, w;
        d2 = fmaxf(aq + sqc[tc*4+0] - 2.f * acc[i][0], 0.f);
        w  = __expf(-bws[tc*4+0] * d2);  o.x = f2tf32(w);
        d2 = fmaxf(aq + sqc[tc*4+1] - 2.f * acc[i][1], 0.f);
        w  = __expf(-bws[tc*4+1] * d2);  o.y = f2tf32(w);
        d2 = fmaxf(aq + sqc[tc*4+2] - 2.f * acc[i][2], 0.f);
        w  = __expf(-bws[tc*4+2] * d2);  o.z = f2tf32(w);
        d2 = fmaxf(aq + sqc[tc*4+3] - 2.f * acc[i][3], 0.f);
        w  = __expf(-bws[tc*4+3] * d2);  o.w = f2tf32(w);
        *(uint4*)(g_W + (size_t)(gb + i) * KDIM + gk) = o;
    }
}

// ---------------------------------------------------------------------------
// Phase 2: out[8192,4096] = W[8192,1024] @ G[1024,4096]  (+ 0.001 on diag)
// mma.sync.m16n8k8 tf32, BM=128 BN=128 BK=16, 8 warps (4x2), warp tile 32x64,
// double-buffered cp.async pipeline.
// ---------------------------------------------------------------------------
#define BM 128
#define BN 128
#define BK 16
#define ASTRIDE 20     // 16 + 4 pad -> conflict-free mma A loads
#define BSTRIDE 132    // 128 + 4 pad
#define NKITER (KDIM / BK)

__device__ __forceinline__ void cp_async16(float* dst, const float* src) {
    uint32_t s = (uint32_t)__cvta_generic_to_shared(dst);
    asm volatile("cp.async.cg.shared.global [%0], [%1], 16;\n" :: "r"(s), "l"(src));
}

__device__ __forceinline__ void mma_tf32(float* c, const uint32_t* a, const uint32_t* b) {
    asm volatile(
        "mma.sync.aligned.m16n8k8.row.col.f32.tf32.tf32.f32 "
        "{%0,%1,%2,%3}, {%4,%5,%6,%7}, {%8,%9}, {%0,%1,%2,%3};\n"
        : "+f"(c[0]), "+f"(c[1]), "+f"(c[2]), "+f"(c[3])
        : "r"(a[0]), "r"(a[1]), "r"(a[2]), "r"(a[3]), "r"(b[0]), "r"(b[1]));
}

__global__ __launch_bounds__(256) void gemm_kernel(float* __restrict__ out) {
    __shared__ float As[2][BM * ASTRIDE];   // 2 * 128*20 floats
    __shared__ float Bs[2][BK * BSTRIDE];   // 2 * 16*132 floats

    int t   = threadIdx.x;
    int bn0 = blockIdx.x * BN;
    int bm0 = blockIdx.y * BM;

    int lane = t & 31, w = t >> 5;
    int wr = w & 3, wc = w >> 2;       // 4x2 warp grid
    int gid = lane >> 2, tig = lane & 3;

    float acc[2][8][4];
#pragma unroll
    for (int mt = 0; mt < 2; mt++)
#pragma unroll
        for (int nt = 0; nt < 8; nt++)
#pragma unroll
            for (int v = 0; v < 4; v++) acc[mt][nt][v] = 0.f;

    // Per-thread load coords (A: 512 chunks of float4, 4/row; B: 512 chunks, 32/row)
    int a_r = (t * 2) >> 2;            // will iterate 2 chunks: t*2, t*2+1
    (void)a_r;

    auto load_stage = [&](int kt, int s) {
        const float* wg = g_W + (size_t)bm0 * KDIM + kt * BK;
        const float* gg = g_G + (size_t)(kt * BK) * NDIM + bn0;
        float* as = As[s];
        float* bs = Bs[s];
#pragma unroll
        for (int i = 0; i < 2; i++) {
            int ch = t + i * 256;      // 0..511
            int r  = ch >> 2;          // 128 rows, 4 chunks/row
            int cc = ch & 3;
            cp_async16(as + r * ASTRIDE + cc * 4, wg + (size_t)r * KDIM + cc * 4);
        }
#pragma unroll
        for (int i = 0; i < 2; i++) {
            int ch = t + i * 256;      // 0..511
            int r  = ch >> 5;          // 16 rows, 32 chunks/row
            int cc = ch & 31;
            cp_async16(bs + r * BSTRIDE + cc * 4, gg + (size_t)r * NDIM + cc * 4);
        }
        asm volatile("cp.async.commit_group;\n");
    };

    load_stage(0, 0);

    for (int kt = 0; kt < NKITER; kt++) {
        asm volatile("cp.async.wait_group 0;\n");
        __syncthreads();
        if (kt + 1 < NKITER) load_stage(kt + 1, (kt + 1) & 1);

        const float* as = As[kt & 1];
        const float* bs = Bs[kt & 1];

#pragma unroll
        for (int ks = 0; ks < 2; ks++) {
            uint32_t a[2][4];
#pragma unroll
            for (int mt = 0; mt < 2; mt++) {
                const float* p = as + (wr * 32 + mt * 16 + gid) * ASTRIDE + ks * 8 + tig;
                a[mt][0] = __float_as_uint(p[0]);
                a[mt][1] = __float_as_uint(p[8 * ASTRIDE]);
                a[mt][2] = __float_as_uint(p[4]);
                a[mt][3] = __float_as_uint(p[8 * ASTRIDE + 4]);
            }
            uint32_t b[8][2];
#pragma unroll
            for (int nt = 0; nt < 8; nt++) {
                const float* p = bs + (ks * 8 + tig) * BSTRIDE + wc * 64 + nt * 8 + gid;
                b[nt][0] = __float_as_uint(p[0]);
                b[nt][1] = __float_as_uint(p[4 * BSTRIDE]);
            }
#pragma unroll
            for (int mt = 0; mt < 2; mt++)
#pragma unroll
                for (int nt = 0; nt < 8; nt++)
                    mma_tf32(acc[mt][nt], a[mt], b[nt]);
        }
        __syncthreads();
    }

    // Epilogue: write C, add REG_COEF on the (i==j) diagonal (col % 65 == 0)
#pragma unroll
    for (int mt = 0; mt < 2; mt++) {
        int r0 = bm0 + wr * 32 + mt * 16 + gid;
#pragma unroll
        for (int nt = 0; nt < 8; nt++) {
            int col = bn0 + wc * 64 + nt * 8 + 2 * tig;
            float d0 = ((col % 65) == 0) ? REG_COEF : 0.f;
            float d1 = (((col + 1) % 65) == 0) ? REG_COEF : 0.f;
            float2 v01 = make_float2(acc[mt][nt][0] + d0, acc[mt][nt][1] + d1);
            float2 v23 = make_float2(acc[mt][nt][2] + d0, acc[mt][nt][3] + d1);
            *(float2*)(out + (size_t)r0 * NDIM + col) = v01;
            *(float2*)(out + (size_t)(r0 + 8) * NDIM + col) = v23;
        }
    }
}

// ---------------------------------------------------------------------------
extern "C" void kernel_launch(void* const* d_in, const int* in_sizes, int n_in,
                              void* d_out, int out_size)
{
    const float* q  = (const float*)d_in[0];
    const float* c  = (const float*)d_in[1];
    const float* bw = (const float*)d_in[2];
    const float* g  = (const float*)d_in[3];
    float* out = (float*)d_out;

    // Phase 0: tf32-round G (1024*4096 floats, 4/thread)
    convert_g_kernel<<<(KDIM * NDIM) / (256 * 4), 256>>>(g);

    // Phase 1: weights (64x64 tiles)
    weights_kernel<<<dim3(KDIM / 64, BDIM / 64), 256>>>(q, c, bw);

    // Phase 2: GEMM + diagonal regularizer
    gemm_kernel<<<dim3(NDIM / BN, BDIM / BM), 256>>>(out);
}

// round 4
// speedup vs baseline: 1.8160x; 1.8160x over previous
#include <cuda_runtime.h>
#include <cuda_fp16.h>
#include <cstdint>

#define REG_COEF 0.001f

// Problem dims (fixed by the dataset)
#define BDIM 8192
#define KDIM 1024
#define DDIM 64
#define NDIM (DDIM*DDIM)   // 4096

// ---------------------------------------------------------------------------
// GEMM tiling: out[8192,4096] = W[8192,1024] @ G[1024,4096], fp16 mma.sync
// BM=128, BN=128, BK=64, 8 warps (2x4), warp tile 64x32, 4-stage cp.async.
// ---------------------------------------------------------------------------
#define BM 128
#define BN 128
#define BK 64
#define NSTAGES 4
#define NKI (KDIM / BK)        // 16 k-iterations

// smem strides (bytes), padded for conflict-free ldmatrix
#define A_STRIDE 144           // 64 halfs = 128B + 16B pad
#define B_STRIDE 272           // 128 halfs = 256B + 16B pad
#define A_STAGE (BM * A_STRIDE)          // 18432
#define B_STAGE (BK * B_STRIDE)          // 17408
#define STAGE_BYTES (A_STAGE + B_STAGE)  // 35840
#define SMEM_TOTAL (NSTAGES * STAGE_BYTES)  // 143360

// Scratch: W[B,K] half, G half copy [K,N]
__device__ __align__(16) __half g_W[(size_t)BDIM * KDIM];
__device__ __align__(16) __half g_GC[(size_t)KDIM * NDIM];

__device__ __forceinline__ uint32_t smem_u32(const void* p) {
    uint32_t a;
    asm("{ .reg .u64 t; cvta.to.shared.u64 t, %1; cvt.u32.u64 %0, t; }"
        : "=r"(a) : "l"(p));
    return a;
}

__device__ __forceinline__ void cp_async16(uint32_t smem_dst, const void* src) {
    asm volatile("cp.async.cg.shared.global [%0], [%1], 16;\n"
                 :: "r"(smem_dst), "l"(src));
}

__device__ __forceinline__ void ldsm_x4(uint32_t* r, uint32_t addr) {
    asm volatile("ldmatrix.sync.aligned.m8n8.x4.shared.b16 {%0,%1,%2,%3}, [%4];"
                 : "=r"(r[0]), "=r"(r[1]), "=r"(r[2]), "=r"(r[3]) : "r"(addr));
}
__device__ __forceinline__ void ldsm_x2_t(uint32_t* r, uint32_t addr) {
    asm volatile("ldmatrix.sync.aligned.m8n8.x2.trans.shared.b16 {%0,%1}, [%2];"
                 : "=r"(r[0]), "=r"(r[1]) : "r"(addr));
}
__device__ __forceinline__ void mma_f16(float* c, const uint32_t* a, const uint32_t* b) {
    asm volatile(
        "mma.sync.aligned.m16n8k16.row.col.f32.f16.f16.f32 "
        "{%0,%1,%2,%3}, {%4,%5,%6,%7}, {%8,%9}, {%0,%1,%2,%3};\n"
        : "+f"(c[0]), "+f"(c[1]), "+f"(c[2]), "+f"(c[3])
        : "r"(a[0]), "r"(a[1]), "r"(a[2]), "r"(a[3]), "r"(b[0]), "r"(b[1]));
}

// ---------------------------------------------------------------------------
// Phase 0: G fp32 [K,N] -> half [K,N]
// ---------------------------------------------------------------------------
__global__ __launch_bounds__(256) void convert_g_kernel(const float* __restrict__ g) {
    size_t i = ((size_t)blockIdx.x * 256 + threadIdx.x) * 8;
    float4 v0 = *(const float4*)(g + i);
    float4 v1 = *(const float4*)(g + i + 4);
    __half2 h[4];
    h[0] = __floats2half2_rn(v0.x, v0.y);
    h[1] = __floats2half2_rn(v0.z, v0.w);
    h[2] = __floats2half2_rn(v1.x, v1.y);
    h[3] = __floats2half2_rn(v1.z, v1.w);
    *(uint4*)(g_GC + i) = *(uint4*)h;
}

// ---------------------------------------------------------------------------
// Phase 1: W[b,k] = exp(-bw_k * max(||q_b||^2 + ||c_k||^2 - 2 q_b.c_k, 0)) -> half
// ---------------------------------------------------------------------------
__global__ __launch_bounds__(256) void weights_kernel(
    const float* __restrict__ q, const float* __restrict__ c,
    const float* __restrict__ bw)
{
    __shared__ float qs[64][68];
    __shared__ float cs[64][68];
    __shared__ float sqq[64], sqc[64], bws[64];

    int t  = threadIdx.x;
    int bx = blockIdx.x;
    int by = blockIdx.y;

#pragma unroll
    for (int i = 0; i < 4; i++) {
        int ch  = t + i * 256;
        int row = ch >> 4;
        int cc  = ch & 15;
        float4 v = *(const float4*)(q + ((size_t)(by * 64 + row)) * DDIM + cc * 4);
        qs[cc*4+0][row] = v.x; qs[cc*4+1][row] = v.y;
        qs[cc*4+2][row] = v.z; qs[cc*4+3][row] = v.w;
        float4 w = *(const float4*)(c + ((size_t)(bx * 64 + row)) * DDIM + cc * 4);
        cs[cc*4+0][row] = w.x; cs[cc*4+1][row] = w.y;
        cs[cc*4+2][row] = w.z; cs[cc*4+3][row] = w.w;
    }
    if (t < 64) bws[t] = bw[bx * 64 + t];
    __syncthreads();

    if (t < 64) {
        float s = 0.f;
#pragma unroll 8
        for (int kk = 0; kk < 64; kk++) { float v = qs[kk][t]; s = fmaf(v, v, s); }
        sqq[t] = s;
    } else if (t < 128) {
        int r = t - 64;
        float s = 0.f;
#pragma unroll 8
        for (int kk = 0; kk < 64; kk++) { float v = cs[kk][r]; s = fmaf(v, v, s); }
        sqc[r] = s;
    }
    __syncthreads();

    int tr = t >> 4;
    int tc = t & 15;

    float acc[4][4];
#pragma unroll
    for (int i = 0; i < 4; i++)
#pragma unroll
        for (int j = 0; j < 4; j++) acc[i][j] = 0.f;

#pragma unroll 4
    for (int kk = 0; kk < 64; kk++) {
        float4 a = *(const float4*)&qs[kk][tr * 4];
        float4 b = *(const float4*)&cs[kk][tc * 4];
        float av[4] = {a.x, a.y, a.z, a.w};
        float bv[4] = {b.x, b.y, b.z, b.w};
#pragma unroll
        for (int i = 0; i < 4; i++)
#pragma unroll
            for (int j = 0; j < 4; j++)
                acc[i][j] = fmaf(av[i], bv[j], acc[i][j]);
    }

    int gb = by * 64 + tr * 4;
    int gk = bx * 64 + tc * 4;
#pragma unroll
    for (int i = 0; i < 4; i++) {
        float aq = sqq[tr * 4 + i];
        float w0, w1, w2, w3, d2;
        d2 = fmaxf(aq + sqc[tc*4+0] - 2.f * acc[i][0], 0.f);
        w0 = __expf(-bws[tc*4+0] * d2);
        d2 = fmaxf(aq + sqc[tc*4+1] - 2.f * acc[i][1], 0.f);
        w1 = __expf(-bws[tc*4+1] * d2);
        d2 = fmaxf(aq + sqc[tc*4+2] - 2.f * acc[i][2], 0.f);
        w2 = __expf(-bws[tc*4+2] * d2);
        d2 = fmaxf(aq + sqc[tc*4+3] - 2.f * acc[i][3], 0.f);
        w3 = __expf(-bws[tc*4+3] * d2);
        __half2 h[2];
        h[0] = __floats2half2_rn(w0, w1);
        h[1] = __floats2half2_rn(w2, w3);
        *(uint2*)(g_W + (size_t)(gb + i) * KDIM + gk) = *(uint2*)h;
    }
}

// ---------------------------------------------------------------------------
// Phase 2: fp16 tensor-core GEMM + diagonal regularizer
// ---------------------------------------------------------------------------
__global__ __launch_bounds__(256, 1) void gemm_kernel(float* __restrict__ out) {
    extern __shared__ __align__(16) char smem[];
    uint32_t sb = smem_u32(smem);

    int t    = threadIdx.x;
    int lane = t & 31;
    int wid  = t >> 5;
    int wr   = wid & 1;          // m offset 0/64
    int wc   = wid >> 1;         // n offset 0..3 * 32
    int bn0  = blockIdx.x * BN;
    int bm0  = blockIdx.y * BM;

    float acc[4][4][4];          // [mt][nt][v]
#pragma unroll
    for (int mt = 0; mt < 4; mt++)
#pragma unroll
        for (int nt = 0; nt < 4; nt++)
#pragma unroll
            for (int v = 0; v < 4; v++) acc[mt][nt][v] = 0.f;

    const char* wbase = (const char*)g_W  + (size_t)bm0 * KDIM * 2;
    const char* gbase = (const char*)g_GC + (size_t)bn0 * 2;

    auto load_stage = [&](int kt, int slot) {
        uint32_t as = sb + slot * STAGE_BYTES;
        uint32_t bs = as + A_STAGE;
#pragma unroll
        for (int i = 0; i < 4; i++) {
            int ch = t + i * 256;            // 0..1023
            int r  = ch >> 3;                // 128 rows, 8 chunks/row
            int s  = ch & 7;
            cp_async16(as + r * A_STRIDE + s * 16,
                       wbase + (size_t)r * (KDIM * 2) + kt * (BK * 2) + s * 16);
        }
#pragma unroll
        for (int i = 0; i < 4; i++) {
            int ch = t + i * 256;            // 0..1023
            int r  = ch >> 4;                // 64 rows, 16 chunks/row
            int s  = ch & 15;
            cp_async16(bs + r * B_STRIDE + s * 16,
                       gbase + (size_t)(kt * BK + r) * (NDIM * 2) + s * 16);
        }
        asm volatile("cp.async.commit_group;\n");
    };

    load_stage(0, 0);
    load_stage(1, 1);
    load_stage(2, 2);

    // per-thread ldmatrix base offsets
    uint32_t a_off = (wr * 64 + (lane & 15)) * A_STRIDE + (lane >> 4) * 16;
    uint32_t b_off = (lane & 15) * B_STRIDE + wc * 64;

    for (int kt = 0; kt < NKI; kt++) {
        asm volatile("cp.async.wait_group 2;\n");
        __syncthreads();
        if (kt + 3 < NKI) load_stage(kt + 3, (kt + 3) & (NSTAGES - 1));

        uint32_t as = sb + (kt & (NSTAGES - 1)) * STAGE_BYTES;
        uint32_t bs = as + A_STAGE;
        uint32_t abase = as + a_off;
        uint32_t bbase = bs + b_off;

#pragma unroll
        for (int ks = 0; ks < 4; ks++) {
            uint32_t a[4][4], b[4][2];
#pragma unroll
            for (int mt = 0; mt < 4; mt++)
                ldsm_x4(a[mt], abase + mt * (16 * A_STRIDE) + ks * 32);
#pragma unroll
            for (int nt = 0; nt < 4; nt++)
                ldsm_x2_t(b[nt], bbase + ks * (16 * B_STRIDE) + nt * 16);
#pragma unroll
            for (int mt = 0; mt < 4; mt++)
#pragma unroll
                for (int nt = 0; nt < 4; nt++)
                    mma_f16(acc[mt][nt], a[mt], b[nt]);
        }
        __syncthreads();
    }

    // Epilogue: write C, add REG_COEF on the diagonal (out col % 65 == 0)
    int g2  = lane >> 2;
    int tig = lane & 3;
#pragma unroll
    for (int mt = 0; mt < 4; mt++) {
        size_t r0 = (size_t)bm0 + wr * 64 + mt * 16 + g2;
#pragma unroll
        for (int nt = 0; nt < 4; nt++) {
            int col = bn0 + wc * 32 + nt * 8 + 2 * tig;
            float d0 = ((col % 65) == 0) ? REG_COEF : 0.f;
            float d1 = (((col + 1) % 65) == 0) ? REG_COEF : 0.f;
            *(float2*)(out + r0 * NDIM + col) =
                make_float2(acc[mt][nt][0] + d0, acc[mt][nt][1] + d1);
            *(float2*)(out + (r0 + 8) * NDIM + col) =
                make_float2(acc[mt][nt][2] + d0, acc[mt][nt][3] + d1);
        }
    }
}

// ---------------------------------------------------------------------------
extern "C" void kernel_launch(void* const* d_in, const int* in_sizes, int n_in,
                              void* d_out, int out_size)
{
    const float* q  = (const float*)d_in[0];
    const float* c  = (const float*)d_in[1];
    const float* bw = (const float*)d_in[2];
    const float* g  = (const float*)d_in[3];
    float* out = (float*)d_out;

    cudaFuncSetAttribute(gemm_kernel,
                         cudaFuncAttributeMaxDynamicSharedMemorySize, SMEM_TOTAL);

    // Phase 0: convert G to half
    convert_g_kernel<<<(KDIM * (size_t)NDIM) / (256 * 8), 256>>>(g);

    // Phase 1: weights (half output)
    weights_kernel<<<dim3(KDIM / 64, BDIM / 64), 256>>>(q, c, bw);

    // Phase 2: fp16 tensor-core GEMM + diagonal regularizer
    gemm_kernel<<<dim3(NDIM / BN, BDIM / BM), 256, SMEM_TOTAL>>>(out);
}

// round 6
// speedup vs baseline: 2.1984x; 1.2105x over previous
#include <cuda_runtime.h>
#include <cuda_fp16.h>
#include <cstdint>

#define REG_COEF 0.001f

// Problem dims (fixed by the dataset)
#define BDIM 8192
#define KDIM 1024
#define DDIM 64
#define NDIM (DDIM*DDIM)   // 4096

// ---------------------------------------------------------------------------
// GEMM tiling: out[8192,4096] = W[8192,1024] @ G[1024,4096], fp16 mma.sync
// BM=128, BN=128, BK=64, 8 warps (2x4), warp tile 64x32, 3-stage cp.async,
// 2 CTAs/SM to overlap sync/drain bubbles.
// ---------------------------------------------------------------------------
#define BM 128
#define BN 128
#define BK 64
#define NSTAGES 3
#define NKI (KDIM / BK)        // 16 k-iterations

// smem strides (bytes), padded for conflict-free ldmatrix
#define A_STRIDE 144           // 64 halfs = 128B + 16B pad
#define B_STRIDE 272           // 128 halfs = 256B + 16B pad
#define A_STAGE (BM * A_STRIDE)          // 18432
#define B_STAGE (BK * B_STRIDE)          // 17408
#define STAGE_BYTES (A_STAGE + B_STAGE)  // 35840
#define SMEM_TOTAL (NSTAGES * STAGE_BYTES)  // 107520

// Scratch: W[B,K] half, G half copy [K,N]
__device__ __align__(16) __half g_W[(size_t)BDIM * KDIM];
__device__ __align__(16) __half g_GC[(size_t)KDIM * NDIM];

__device__ __forceinline__ uint32_t smem_u32(const void* p) {
    uint32_t a;
    asm("{ .reg .u64 t; cvta.to.shared.u64 t, %1; cvt.u32.u64 %0, t; }"
        : "=r"(a) : "l"(p));
    return a;
}

__device__ __forceinline__ void cp_async16(uint32_t smem_dst, const void* src) {
    asm volatile("cp.async.cg.shared.global [%0], [%1], 16;\n"
                 :: "r"(smem_dst), "l"(src));
}

__device__ __forceinline__ void ldsm_x4(uint32_t* r, uint32_t addr) {
    asm volatile("ldmatrix.sync.aligned.m8n8.x4.shared.b16 {%0,%1,%2,%3}, [%4];"
                 : "=r"(r[0]), "=r"(r[1]), "=r"(r[2]), "=r"(r[3]) : "r"(addr));
}
__device__ __forceinline__ void ldsm_x2_t(uint32_t* r, uint32_t addr) {
    asm volatile("ldmatrix.sync.aligned.m8n8.x2.trans.shared.b16 {%0,%1}, [%2];"
                 : "=r"(r[0]), "=r"(r[1]) : "r"(addr));
}
__device__ __forceinline__ void mma_f16(float* c, const uint32_t* a, const uint32_t* b) {
    asm volatile(
        "mma.sync.aligned.m16n8k16.row.col.f32.f16.f16.f32 "
        "{%0,%1,%2,%3}, {%4,%5,%6,%7}, {%8,%9}, {%0,%1,%2,%3};\n"
        : "+f"(c[0]), "+f"(c[1]), "+f"(c[2]), "+f"(c[3])
        : "r"(a[0]), "r"(a[1]), "r"(a[2]), "r"(a[3]), "r"(b[0]), "r"(b[1]));
}

// ---------------------------------------------------------------------------
// Fused Phase 0+1:
//   blocks [0, 2048):    weights W[b,k] = exp(-bw_k * d2(q_b,c_k)) -> half
//   blocks [2048, 4096): convert G fp32 -> half
// ---------------------------------------------------------------------------
__global__ __launch_bounds__(256) void prep_kernel(
    const float* __restrict__ q, const float* __restrict__ c,
    const float* __restrict__ bw, const float* __restrict__ g)
{
    if (blockIdx.x >= 2048) {
        // ---- convert G ----
        size_t i = ((size_t)(blockIdx.x - 2048) * 256 + threadIdx.x) * 8;
        float4 v0 = *(const float4*)(g + i);
        float4 v1 = *(const float4*)(g + i + 4);
        __half2 h[4];
        h[0] = __floats2half2_rn(v0.x, v0.y);
        h[1] = __floats2half2_rn(v0.z, v0.w);
        h[2] = __floats2half2_rn(v1.x, v1.y);
        h[3] = __floats2half2_rn(v1.z, v1.w);
        *(uint4*)(g_GC + i) = *(uint4*)h;
        return;
    }

    // ---- weights ----
    __shared__ float qs[64][68];
    __shared__ float cs[64][68];
    __shared__ float sqq[64], sqc[64], bws[64];

    int t  = threadIdx.x;
    int bx = blockIdx.x & 15;
    int by = blockIdx.x >> 4;

#pragma unroll
    for (int i = 0; i < 4; i++) {
        int ch  = t + i * 256;
        int row = ch >> 4;
        int cc  = ch & 15;
        float4 v = *(const float4*)(q + ((size_t)(by * 64 + row)) * DDIM + cc * 4);
        qs[cc*4+0][row] = v.x; qs[cc*4+1][row] = v.y;
        qs[cc*4+2][row] = v.z; qs[cc*4+3][row] = v.w;
        float4 w = *(const float4*)(c + ((size_t)(bx * 64 + row)) * DDIM + cc * 4);
        cs[cc*4+0][row] = w.x; cs[cc*4+1][row] = w.y;
        cs[cc*4+2][row] = w.z; cs[cc*4+3][row] = w.w;
    }
    if (t < 64) bws[t] = bw[bx * 64 + t];
    __syncthreads();

    if (t < 64) {
        float s = 0.f;
#pragma unroll 8
        for (int kk = 0; kk < 64; kk++) { float v = qs[kk][t]; s = fmaf(v, v, s); }
        sqq[t] = s;
    } else if (t < 128) {
        int r = t - 64;
        float s = 0.f;
#pragma unroll 8
        for (int kk = 0; kk < 64; kk++) { float v = cs[kk][r]; s = fmaf(v, v, s); }
        sqc[r] = s;
    }
    __syncthreads();

    int tr = t >> 4;
    int tc = t & 15;

    float acc[4][4];
#pragma unroll
    for (int i = 0; i < 4; i++)
#pragma unroll
        for (int j = 0; j < 4; j++) acc[i][j] = 0.f;

#pragma unroll 4
    for (int kk = 0; kk < 64; kk++) {
        float4 a = *(const float4*)&qs[kk][tr * 4];
        float4 b = *(const float4*)&cs[kk][tc * 4];
        float av[4] = {a.x, a.y, a.z, a.w};
        float bv[4] = {b.x, b.y, b.z, b.w};
#pragma unroll
        for (int i = 0; i < 4; i++)
#pragma unroll
            for (int j = 0; j < 4; j++)
                acc[i][j] = fmaf(av[i], bv[j], acc[i][j]);
    }

    int gb = by * 64 + tr * 4;
    int gk = bx * 64 + tc * 4;
#pragma unroll
    for (int i = 0; i < 4; i++) {
        float aq = sqq[tr * 4 + i];
        float w0, w1, w2, w3, d2;
        d2 = fmaxf(aq + sqc[tc*4+0] - 2.f * acc[i][0], 0.f);
        w0 = __expf(-bws[tc*4+0] * d2);
        d2 = fmaxf(aq + sqc[tc*4+1] - 2.f * acc[i][1], 0.f);
        w1 = __expf(-bws[tc*4+1] * d2);
        d2 = fmaxf(aq + sqc[tc*4+2] - 2.f * acc[i][2], 0.f);
        w2 = __expf(-bws[tc*4+2] * d2);
        d2 = fmaxf(aq + sqc[tc*4+3] - 2.f * acc[i][3], 0.f);
        w3 = __expf(-bws[tc*4+3] * d2);
        __half2 h[2];
        h[0] = __floats2half2_rn(w0, w1);
        h[1] = __floats2half2_rn(w2, w3);
        *(uint2*)(g_W + (size_t)(gb + i) * KDIM + gk) = *(uint2*)h;
    }
}

// ---------------------------------------------------------------------------
// Phase 2: fp16 tensor-core GEMM + diagonal regularizer (2 CTAs/SM)
// ---------------------------------------------------------------------------
__global__ __launch_bounds__(256, 2) void gemm_kernel(float* __restrict__ out) {
    extern __shared__ __align__(16) char smem[];
    uint32_t sb = smem_u32(smem);

    int t    = threadIdx.x;
    int lane = t & 31;
    int wid  = t >> 5;
    int wr   = wid & 1;          // m offset 0/64
    int wc   = wid >> 1;         // n offset 0..3 * 32
    int bn0  = blockIdx.x * BN;
    int bm0  = blockIdx.y * BM;

    float acc[4][4][4];          // [mt][nt][v]
#pragma unroll
    for (int mt = 0; mt < 4; mt++)
#pragma unroll
        for (int nt = 0; nt < 4; nt++)
#pragma unroll
            for (int v = 0; v < 4; v++) acc[mt][nt][v] = 0.f;

    const char* wbase = (const char*)g_W  + (size_t)bm0 * KDIM * 2;
    const char* gbase = (const char*)g_GC + (size_t)bn0 * 2;

    auto load_stage = [&](int kt, int slot) {
        uint32_t as = sb + slot * STAGE_BYTES;
        uint32_t bs = as + A_STAGE;
#pragma unroll
        for (int i = 0; i < 4; i++) {
            int ch = t + i * 256;            // 0..1023
            int r  = ch >> 3;                // 128 rows, 8 chunks/row
            int s  = ch & 7;
            cp_async16(as + r * A_STRIDE + s * 16,
                       wbase + (size_t)r * (KDIM * 2) + kt * (BK * 2) + s * 16);
        }
#pragma unroll
        for (int i = 0; i < 4; i++) {
            int ch = t + i * 256;            // 0..1023
            int r  = ch >> 4;                // 64 rows, 16 chunks/row
            int s  = ch & 15;
            cp_async16(bs + r * B_STRIDE + s * 16,
                       gbase + (size_t)(kt * BK + r) * (NDIM * 2) + s * 16);
        }
    };

    // Prologue: stages 0 and 1 (groups 0 and 1)
    load_stage(0, 0);
    asm volatile("cp.async.commit_group;\n");
    load_stage(1, 1);
    asm volatile("cp.async.commit_group;\n");

    // per-thread ldmatrix base offsets
    uint32_t a_off = (wr * 64 + (lane & 15)) * A_STRIDE + (lane >> 4) * 16;
    uint32_t b_off = (lane & 15) * B_STRIDE + wc * 64;

    int slot = 0;       // slot of stage kt
    int lslot = 2;      // slot of stage kt+2
    for (int kt = 0; kt < NKI; kt++) {
        // groups committed so far: 0..kt+1; allow kt+1 pending -> stage kt ready
        asm volatile("cp.async.wait_group 1;\n");
        __syncthreads();

        // Load stage kt+2 (slot reuse distance 3: last readers finished
        // before the sync above). Always commit so group indexing holds.
        if (kt + 2 < NKI) load_stage(kt + 2, lslot);
        asm volatile("cp.async.commit_group;\n");

        uint32_t as = sb + slot * STAGE_BYTES;
        uint32_t bs = as + A_STAGE;
        uint32_t abase = as + a_off;
        uint32_t bbase = bs + b_off;

#pragma unroll
        for (int ks = 0; ks < 4; ks++) {
            uint32_t a[4][4], b[4][2];
#pragma unroll
            for (int mt = 0; mt < 4; mt++)
                ldsm_x4(a[mt], abase + mt * (16 * A_STRIDE) + ks * 32);
#pragma unroll
            for (int nt = 0; nt < 4; nt++)
                ldsm_x2_t(b[nt], bbase + ks * (16 * B_STRIDE) + nt * 16);
#pragma unroll
            for (int mt = 0; mt < 4; mt++)
#pragma unroll
                for (int nt = 0; nt < 4; nt++)
                    mma_f16(acc[mt][nt], a[mt], b[nt]);
        }

        slot  = (slot  == 2) ? 0 : slot + 1;
        lslot = (lslot == 2) ? 0 : lslot + 1;
    }

    // Epilogue: write C, add REG_COEF on the diagonal (out col % 65 == 0)
    int g2  = lane >> 2;
    int tig = lane & 3;
#pragma unroll
    for (int mt = 0; mt < 4; mt++) {
        size_t r0 = (size_t)bm0 + wr * 64 + mt * 16 + g2;
#pragma unroll
        for (int nt = 0; nt < 4; nt++) {
            int col = bn0 + wc * 32 + nt * 8 + 2 * tig;
            float d0 = ((col % 65) == 0) ? REG_COEF : 0.f;
            float d1 = (((col + 1) % 65) == 0) ? REG_COEF : 0.f;
            *(float2*)(out + r0 * NDIM + col) =
                make_float2(acc[mt][nt][0] + d0, acc[mt][nt][1] + d1);
            *(float2*)(out + (r0 + 8) * NDIM + col) =
                make_float2(acc[mt][nt][2] + d0, acc[mt][nt][3] + d1);
        }
    }
}

// ---------------------------------------------------------------------------
extern "C" void kernel_launch(void* const* d_in, const int* in_sizes, int n_in,
                              void* d_out, int out_size)
{
    const float* q  = (const float*)d_in[0];
    const float* c  = (const float*)d_in[1];
    const float* bw = (const float*)d_in[2];
    const float* g  = (const float*)d_in[3];
    float* out = (float*)d_out;

    cudaFuncSetAttribute(gemm_kernel,
                         cudaFuncAttributeMaxDynamicSharedMemorySize, SMEM_TOTAL);

    // Fused phase 0+1: weights (2048 blocks) + G convert (2048 blocks)
    prep_kernel<<<4096, 256>>>(q, c, bw, g);

    // Phase 2: fp16 tensor-core GEMM + diagonal regularizer
    gemm_kernel<<<dim3(NDIM / BN, BDIM / BM), 256, SMEM_TOTAL>>>(out);
}